// round 15
// baseline (speedup 1.0000x reference)
#include <cuda_runtime.h>
#include <cuda_fp16.h>
#include <stdint.h>
#include <math.h>

#define D_MODEL 1024
#define NH 16
#define DK 64
#define BATCH 2
#define LSEQ 2048
#define MTOT (BATCH*LSEQ)   // 4096
#define HSZ ((size_t)BATCH*NH*LSEQ*DK)

#define QSCALE (0.125f * 1.4426950408889634f)

// ---------------- scratch ----------------
__device__ __half g_ahi[(size_t)MTOT*D_MODEL];
__device__ __half g_alo[(size_t)MTOT*D_MODEL];
__device__ __half g_bhi[(size_t)MTOT*D_MODEL];
__device__ __half g_blo[(size_t)MTOT*D_MODEL];
__device__ __half g_chi[(size_t)MTOT*D_MODEL];
__device__ __half g_clo[(size_t)MTOT*D_MODEL];
__device__ __half g_wthi[4][(size_t)D_MODEL*D_MODEL];
__device__ __half g_wtlo[4][(size_t)D_MODEL*D_MODEL];
__device__ __half g_qhh[HSZ];
__device__ __half g_qhl[HSZ];
__device__ __half g_khh[HSZ];
__device__ __half g_khl[HSZ];
__device__ __half g_vhh[HSZ];

// ---------------- helpers ----------------
__device__ __forceinline__ uint32_t smem_u32(const void* p) {
    uint32_t a;
    asm("{ .reg .u64 t; cvta.to.shared.u64 t, %1; cvt.u32.u64 %0, t; }" : "=r"(a) : "l"(p));
    return a;
}
__device__ __forceinline__ void cp16(uint32_t dst, const void* src) {
    asm volatile("cp.async.cg.shared.global [%0], [%1], 16;" :: "r"(dst), "l"(src) : "memory");
}
__device__ __forceinline__ void ldsm4(uint32_t& r0, uint32_t& r1, uint32_t& r2, uint32_t& r3, uint32_t a) {
    asm volatile("ldmatrix.sync.aligned.m8n8.x4.shared.b16 {%0,%1,%2,%3}, [%4];"
                 : "=r"(r0), "=r"(r1), "=r"(r2), "=r"(r3) : "r"(a));
}
__device__ __forceinline__ void ldsm4t(uint32_t& r0, uint32_t& r1, uint32_t& r2, uint32_t& r3, uint32_t a) {
    asm volatile("ldmatrix.sync.aligned.m8n8.x4.trans.shared.b16 {%0,%1,%2,%3}, [%4];"
                 : "=r"(r0), "=r"(r1), "=r"(r2), "=r"(r3) : "r"(a));
}
__device__ __forceinline__ void mma16816(float* c, const uint32_t* a, uint32_t b0, uint32_t b1) {
    asm volatile("mma.sync.aligned.m16n8k16.row.col.f32.f16.f16.f32 "
                 "{%0,%1,%2,%3},{%4,%5,%6,%7},{%8,%9},{%0,%1,%2,%3};"
                 : "+f"(c[0]), "+f"(c[1]), "+f"(c[2]), "+f"(c[3])
                 : "r"(a[0]), "r"(a[1]), "r"(a[2]), "r"(a[3]), "r"(b0), "r"(b1));
}
__device__ __forceinline__ float ex2f(float x) {
    float y;
    asm("ex2.approx.ftz.f32 %0, %1;" : "=f"(y) : "f"(x));
    return y;
}

// ---------------- fused prep kernels ----------------
__global__ __launch_bounds__(256) void split_act3(
        const float* __restrict__ q, const float* __restrict__ k, const float* __restrict__ v,
        __half* __restrict__ h0, __half* __restrict__ l0,
        __half* __restrict__ h1, __half* __restrict__ l1,
        __half* __restrict__ h2, __half* __restrict__ l2) {
    const float* x = (blockIdx.y == 0) ? q : (blockIdx.y == 1) ? k : v;
    __half* hi = (blockIdx.y == 0) ? h0 : (blockIdx.y == 1) ? h1 : h2;
    __half* lo = (blockIdx.y == 0) ? l0 : (blockIdx.y == 1) ? l1 : l2;
    int i = (blockIdx.x * 256 + threadIdx.x) * 4;
    float4 w = *(const float4*)(x + i);
    __half a0 = __float2half_rn(w.x), a1 = __float2half_rn(w.y);
    __half a2 = __float2half_rn(w.z), a3 = __float2half_rn(w.w);
    __half2 H0 = {a0, a1}, H1 = {a2, a3};
    __half2 L0 = {__float2half_rn(w.x - __half2float(a0)), __float2half_rn(w.y - __half2float(a1))};
    __half2 L1 = {__float2half_rn(w.z - __half2float(a2)), __float2half_rn(w.w - __half2float(a3))};
    *(__half2*)(hi + i) = H0; *(__half2*)(hi + i + 2) = H1;
    *(__half2*)(lo + i) = L0; *(__half2*)(lo + i + 2) = L1;
}

__global__ __launch_bounds__(256) void trans_split4(
        const float* __restrict__ W0, const float* __restrict__ W1,
        const float* __restrict__ W2, const float* __restrict__ W3,
        __half* __restrict__ Thi, __half* __restrict__ Tlo) {
    const size_t WSZ = (size_t)D_MODEL * D_MODEL;
    const float* W = (blockIdx.z == 0) ? W0 : (blockIdx.z == 1) ? W1 : (blockIdx.z == 2) ? W2 : W3;
    __half* thi = Thi + blockIdx.z * WSZ;
    __half* tlo = Tlo + blockIdx.z * WSZ;
    __shared__ float s[32][33];
    int tx = threadIdx.x & 31, ty = threadIdx.x >> 5;
    int x = blockIdx.x * 32 + tx;
    #pragma unroll
    for (int i = 0; i < 4; i++) {
        int y = blockIdx.y * 32 + ty + i * 8;
        s[ty + i * 8][tx] = W[(size_t)y * D_MODEL + x];
    }
    __syncthreads();
    #pragma unroll
    for (int i = 0; i < 4; i++) {
        int n = blockIdx.x * 32 + ty + i * 8;
        int k = blockIdx.y * 32 + tx;
        float f = s[tx][ty + i * 8];
        __half h = __float2half_rn(f);
        thi[(size_t)n * D_MODEL + k] = h;
        tlo[(size_t)n * D_MODEL + k] = __float2half_rn(f - __half2float(h));
    }
}

// ---------------- HMMA GEMM: BM=128 BN=256 BK=32, 512 threads ----------------
// 3-slot ring, single barrier/stage, loads issued before compute.
// Slot (stride 80B/row): Ahi 10240 | Alo 10240 | Bhi 20480 | Blo 20480 = 61440
#define GSLOT 61440
#define G_SMEM (3*GSLOT)   // 184320
#define GA_LO 10240
#define GB_HI 20480
#define GB_LO 40960

// MODE 0: head layout hi+lo; MODE 2: head layout hi only; MODE 1: fp32 [M,N]
template<int MODE>
__global__ __launch_bounds__(512) void gemm_hmma(const __half* __restrict__ Ahi, const __half* __restrict__ Alo,
                                                 const __half* __restrict__ Bhi, const __half* __restrict__ Blo,
                                                 const float* __restrict__ bias, float* __restrict__ Cf,
                                                 __half* __restrict__ Chi, __half* __restrict__ Clo,
                                                 float scale) {
    extern __shared__ char sm[];
    const uint32_t sb = smem_u32(sm);
    const int t = threadIdx.x, lane = t & 31, wid = t >> 5;   // 16 warps
    const int warpM = wid >> 2, warpN = wid & 3;              // 4x4
    const int m0 = blockIdx.y * 128, n0 = blockIdx.x * 256;

    float acc[2][8][4];
    #pragma unroll
    for (int i = 0; i < 2; i++)
        #pragma unroll
        for (int j = 0; j < 8; j++)
            #pragma unroll
            for (int r = 0; r < 4; r++) acc[i][j][r] = 0.f;

    auto load_stage = [&](int s) {
        const uint32_t soff = sb + (uint32_t)(s % 3) * GSLOT;
        const int k0 = s * 32;
        {   // A: 128 rows x 4 segs (16B), hi+lo — 512 jobs
            int row = t >> 2, seg = t & 3;
            uint32_t d = soff + row * 80 + seg * 16;
            size_t gi = (size_t)(m0 + row) * D_MODEL + k0 + seg * 8;
            cp16(d,         Ahi + gi);
            cp16(d + GA_LO, Alo + gi);
        }
        #pragma unroll
        for (int it = 0; it < 2; it++) {   // B: 256 rows x 4 segs, hi+lo — 1024 jobs
            int c = t + it * 512;
            int row = c >> 2, seg = c & 3;
            uint32_t d = soff + GB_HI + row * 80 + seg * 16;
            size_t gj = (size_t)(n0 + row) * D_MODEL + k0 + seg * 8;
            cp16(d,                   Bhi + gj);
            cp16(d + (GB_LO - GB_HI), Blo + gj);
        }
        asm volatile("cp.async.commit_group;" ::: "memory");
    };

    load_stage(0);
    load_stage(1);

    const int mat = lane >> 3, mrow = lane & 7;
    for (int s = 0; s < 32; s++) {
        if (s < 30) asm volatile("cp.async.wait_group 1;" ::: "memory");
        else        asm volatile("cp.async.wait_group 0;" ::: "memory");
        __syncthreads();                 // slot (s-1)%3 fully consumed by all warps
        if (s + 2 < 32) load_stage(s + 2);   // refills slot (s+2)%3 == (s-1)%3
        const uint32_t soff = sb + (uint32_t)(s % 3) * GSLOT;
        #pragma unroll
        for (int kk = 0; kk < 2; kk++) {
            uint32_t ah[2][4], al[2][4];
            #pragma unroll
            for (int mt = 0; mt < 2; mt++) {
                int aRow = warpM * 32 + mt * 16 + (mat & 1) * 8 + mrow;
                int aK = kk * 16 + (mat >> 1) * 8;
                uint32_t ad = soff + aRow * 80 + aK * 2;
                ldsm4(ah[mt][0], ah[mt][1], ah[mt][2], ah[mt][3], ad);
                ldsm4(al[mt][0], al[mt][1], al[mt][2], al[mt][3], ad + GA_LO);
            }
            #pragma unroll
            for (int nt2 = 0; nt2 < 4; nt2++) {
                int bRow = warpN * 64 + nt2 * 16 + (mat >> 1) * 8 + mrow;
                int bK = kk * 16 + (mat & 1) * 8;
                uint32_t bd = soff + GB_HI + bRow * 80 + bK * 2;
                uint32_t bh[4], bl[4];
                ldsm4(bh[0], bh[1], bh[2], bh[3], bd);
                ldsm4(bl[0], bl[1], bl[2], bl[3], bd + (GB_LO - GB_HI));
                // 3-pass ordering: same-accumulator MMAs are 4 issues apart
                #pragma unroll
                for (int mt = 0; mt < 2; mt++)
                    #pragma unroll
                    for (int ntl = 0; ntl < 2; ntl++)
                        mma16816(acc[mt][nt2 * 2 + ntl], ah[mt], bh[ntl * 2], bh[ntl * 2 + 1]);
                #pragma unroll
                for (int mt = 0; mt < 2; mt++)
                    #pragma unroll
                    for (int ntl = 0; ntl < 2; ntl++)
                        mma16816(acc[mt][nt2 * 2 + ntl], al[mt], bh[ntl * 2], bh[ntl * 2 + 1]);
                #pragma unroll
                for (int mt = 0; mt < 2; mt++)
                    #pragma unroll
                    for (int ntl = 0; ntl < 2; ntl++)
                        mma16816(acc[mt][nt2 * 2 + ntl], ah[mt], bl[ntl * 2], bl[ntl * 2 + 1]);
            }
        }
    }

    #pragma unroll
    for (int mt = 0; mt < 2; mt++) {
        #pragma unroll
        for (int nt = 0; nt < 8; nt++) {
            int row = m0 + warpM * 32 + mt * 16 + (lane >> 2);
            int col = n0 + warpN * 64 + nt * 8 + 2 * (lane & 3);
            float b0 = bias[col], b1 = bias[col + 1];
            #pragma unroll
            for (int h = 0; h < 2; h++) {
                int m = row + h * 8;
                float v0 = acc[mt][nt][h * 2] + b0;
                float v1 = acc[mt][nt][h * 2 + 1] + b1;
                if (MODE == 1) {
                    float2 v = {v0, v1};
                    *(float2*)(Cf + (size_t)m * D_MODEL + col) = v;
                } else {
                    v0 *= scale; v1 *= scale;
                    int bb = m >> 11, l = m & (LSEQ - 1);
                    int hh = col >> 6, d = col & (DK - 1);
                    size_t idx = (((size_t)(bb * NH + hh)) * LSEQ + l) * DK + d;
                    __half2 H = __floats2half2_rn(v0, v1);
                    *(__half2*)(Chi + idx) = H;
                    if (MODE == 0) {
                        float2 hf = __half22float2(H);
                        __half2 L = __floats2half2_rn(v0 - hf.x, v1 - hf.y);
                        *(__half2*)(Clo + idx) = L;
                    }
                }
            }
        }
    }
}

// ---------------- HMMA flash attention (R14 exact) ----------------
#define AT_QL 18432
#define AT_ST 36864
#define AT_STSZ 27648
#define AT_KL 9216
#define AT_VH 18432
#define ATT_SMEM2 (AT_ST + 4*AT_STSZ)   // 147456

__global__ __launch_bounds__(256, 1) void attn_hmma(
    const __half* __restrict__ Qhi, const __half* __restrict__ Qlo,
    const __half* __restrict__ Khi, const __half* __restrict__ Klo,
    const __half* __restrict__ Vhi,
    __half* __restrict__ Ohi, __half* __restrict__ Olo) {
    extern __shared__ char sm[];
    const uint32_t sb = smem_u32(sm);
    const int t = threadIdx.x, lane = t & 31, wid = t >> 5;
    const int bh = blockIdx.y, q0 = blockIdx.x * 128;
    const size_t base = (size_t)bh * LSEQ * DK;
    const int mat = lane >> 3, mrow = lane & 7;

    for (int c = t; c < 1024; c += 256) {
        int r = c >> 3, seg = c & 7;
        uint32_t d = sb + r * 144 + seg * 16;
        size_t off = base + (size_t)(q0 + r) * DK + seg * 8;
        cp16(d, Qhi + off);
        cp16(d + AT_QL, Qlo + off);
    }
    asm volatile("cp.async.commit_group;" ::: "memory");

    auto load_stage = [&](int s) {
        const size_t kb = base + (size_t)(s * 64) * DK;
        const uint32_t st = sb + AT_ST + (s & 3) * AT_STSZ;
        #pragma unroll
        for (int it = 0; it < 2; it++) {
            int c = t + it * 256;          // 64 rows x 8 segs
            int r = c >> 3, seg = c & 7;
            uint32_t d = st + r * 144 + seg * 16;
            size_t off = kb + (size_t)r * DK + seg * 8;
            cp16(d,          Khi + off);
            cp16(d + AT_KL,  Klo + off);
            cp16(d + AT_VH,  Vhi + off);
        }
        asm volatile("cp.async.commit_group;" ::: "memory");
    };
    load_stage(0);
    load_stage(1);
    load_stage(2);

    asm volatile("cp.async.wait_group 3;" ::: "memory");   // Q landed
    __syncthreads();
    uint32_t qhf[4][4], qlf[4][4];
    #pragma unroll
    for (int kt = 0; kt < 4; kt++) {
        int aRow = wid * 16 + (mat & 1) * 8 + mrow;
        int aK = kt * 16 + (mat >> 1) * 8;
        uint32_t ad = sb + aRow * 144 + aK * 2;
        ldsm4(qhf[kt][0], qhf[kt][1], qhf[kt][2], qhf[kt][3], ad);
        ldsm4(qlf[kt][0], qlf[kt][1], qlf[kt][2], qlf[kt][3], ad + AT_QL);
    }

    float o[8][4];
    #pragma unroll
    for (int i = 0; i < 8; i++)
        #pragma unroll
        for (int j = 0; j < 4; j++) o[i][j] = 0.f;
    float l0 = 0.f, l1 = 0.f;

    for (int s = 0; s < 32; s++) {
        if (s < 29) asm volatile("cp.async.wait_group 2;" ::: "memory");
        else        asm volatile("cp.async.wait_group 0;" ::: "memory");
        __syncthreads();   // all warps done with slot (s-1)&3; safe to refill it
        if (s + 3 < 32) load_stage(s + 3);
        const uint32_t st = sb + AT_ST + (s & 3) * AT_STSZ;

        float c[8][4];
        #pragma unroll
        for (int i = 0; i < 8; i++)
            #pragma unroll
            for (int j = 0; j < 4; j++) c[i][j] = 0.f;
        #pragma unroll
        for (int kt = 0; kt < 4; kt++) {
            #pragma unroll
            for (int ntp = 0; ntp < 4; ntp++) {
                int bRow = ntp * 16 + (mat >> 1) * 8 + mrow;
                int bK = kt * 16 + (mat & 1) * 8;
                uint32_t bd = st + bRow * 144 + bK * 2;
                uint32_t kh4[4], kl4[4];
                ldsm4(kh4[0], kh4[1], kh4[2], kh4[3], bd);
                ldsm4(kl4[0], kl4[1], kl4[2], kl4[3], bd + AT_KL);
                #pragma unroll
                for (int sub = 0; sub < 2; sub++) {
                    float* cc = c[ntp * 2 + sub];
                    mma16816(cc, qhf[kt], kh4[sub * 2], kh4[sub * 2 + 1]);
                    mma16816(cc, qlf[kt], kh4[sub * 2], kh4[sub * 2 + 1]);
                    mma16816(cc, qhf[kt], kl4[sub * 2], kl4[sub * 2 + 1]);
                }
            }
        }
        #pragma unroll
        for (int nt = 0; nt < 8; nt++) {
            #pragma unroll
            for (int j = 0; j < 4; j++) c[nt][j] = ex2f(c[nt][j]);
            l0 += c[nt][0] + c[nt][1];
            l1 += c[nt][2] + c[nt][3];
        }
        #pragma unroll
        for (int kt = 0; kt < 4; kt++) {
            uint32_t pah[4];
            #pragma unroll
            for (int half = 0; half < 2; half++) {
                float* e = c[kt * 2 + half];
                __half2 h0 = __floats2half2_rn(e[0], e[1]);
                __half2 h1 = __floats2half2_rn(e[2], e[3]);
                pah[half * 2]     = *(uint32_t*)&h0;
                pah[half * 2 + 1] = *(uint32_t*)&h1;
            }
            #pragma unroll
            for (int ntp = 0; ntp < 4; ntp++) {
                int vRow = kt * 16 + (mat & 1) * 8 + mrow;
                int vCol = ntp * 16 + (mat >> 1) * 8;
                uint32_t vd = st + AT_VH + vRow * 144 + vCol * 2;
                uint32_t vh4[4];
                ldsm4t(vh4[0], vh4[1], vh4[2], vh4[3], vd);
                #pragma unroll
                for (int sub = 0; sub < 2; sub++) {
                    float* oo = o[ntp * 2 + sub];
                    mma16816(oo, pah, vh4[sub * 2], vh4[sub * 2 + 1]);
                }
            }
        }
    }

    l0 += __shfl_xor_sync(0xffffffffu, l0, 1);
    l0 += __shfl_xor_sync(0xffffffffu, l0, 2);
    l1 += __shfl_xor_sync(0xffffffffu, l1, 1);
    l1 += __shfl_xor_sync(0xffffffffu, l1, 2);
    float inv0 = 1.f / l0, inv1 = 1.f / l1;

    const int b = bh >> 4, h = bh & 15;
    const int row0 = q0 + wid * 16 + (lane >> 2);
    const int colb = h * 64 + 2 * (lane & 3);
    #pragma unroll
    for (int nt = 0; nt < 8; nt++) {
        int col = colb + nt * 8;
        float v0 = o[nt][0] * inv0, v1 = o[nt][1] * inv0;
        float v2 = o[nt][2] * inv1, v3 = o[nt][3] * inv1;
        __half2 H0 = __floats2half2_rn(v0, v1);
        __half2 H1 = __floats2half2_rn(v2, v3);
        float2 f0 = __half22float2(H0), f1 = __half22float2(H1);
        __half2 L0 = __floats2half2_rn(v0 - f0.x, v1 - f0.y);
        __half2 L1 = __floats2half2_rn(v2 - f1.x, v3 - f1.y);
        size_t i0 = ((size_t)(b * LSEQ + row0)) * D_MODEL + col;
        size_t i1 = ((size_t)(b * LSEQ + row0 + 8)) * D_MODEL + col;
        *(__half2*)(Ohi + i0) = H0; *(__half2*)(Olo + i0) = L0;
        *(__half2*)(Ohi + i1) = H1; *(__half2*)(Olo + i1) = L1;
    }
}

// ---------------------------------------------------------------------------
extern "C" void kernel_launch(void* const* d_in, const int* in_sizes, int n_in,
                              void* d_out, int out_size) {
    const float* q  = (const float*)d_in[0];
    const float* k  = (const float*)d_in[1];
    const float* v  = (const float*)d_in[2];
    const float* Wq = (const float*)d_in[3];
    const float* bq = (const float*)d_in[4];
    const float* Wk = (const float*)d_in[5];
    const float* bk = (const float*)d_in[6];
    const float* Wv = (const float*)d_in[7];
    const float* bv = (const float*)d_in[8];
    const float* Wo = (const float*)d_in[9];
    const float* bo = (const float*)d_in[10];
    float* out = (float*)d_out;

    __half *ahi, *alo, *bhi, *blo, *chi, *clo, *wthi, *wtlo;
    __half *qhh, *qhl, *khh, *khl, *vhh;
    cudaGetSymbolAddress((void**)&ahi, g_ahi);
    cudaGetSymbolAddress((void**)&alo, g_alo);
    cudaGetSymbolAddress((void**)&bhi, g_bhi);
    cudaGetSymbolAddress((void**)&blo, g_blo);
    cudaGetSymbolAddress((void**)&chi, g_chi);
    cudaGetSymbolAddress((void**)&clo, g_clo);
    cudaGetSymbolAddress((void**)&wthi, g_wthi);
    cudaGetSymbolAddress((void**)&wtlo, g_wtlo);
    cudaGetSymbolAddress((void**)&qhh, g_qhh);
    cudaGetSymbolAddress((void**)&qhl, g_qhl);
    cudaGetSymbolAddress((void**)&khh, g_khh);
    cudaGetSymbolAddress((void**)&khl, g_khl);
    cudaGetSymbolAddress((void**)&vhh, g_vhh);
    const size_t WSZ = (size_t)D_MODEL * D_MODEL;

    static bool attr_set = false;
    if (!attr_set) {
        cudaFuncSetAttribute(gemm_hmma<0>, cudaFuncAttributeMaxDynamicSharedMemorySize, G_SMEM);
        cudaFuncSetAttribute(gemm_hmma<1>, cudaFuncAttributeMaxDynamicSharedMemorySize, G_SMEM);
        cudaFuncSetAttribute(gemm_hmma<2>, cudaFuncAttributeMaxDynamicSharedMemorySize, G_SMEM);
        cudaFuncSetAttribute(attn_hmma, cudaFuncAttributeMaxDynamicSharedMemorySize, ATT_SMEM2);
        attr_set = true;
    }

    trans_split4<<<dim3(32, 32, 4), 256>>>(Wq, Wk, Wv, Wo, wthi, wtlo);
    split_act3<<<dim3(4096, 3), 256>>>(q, k, v, ahi, alo, bhi, blo, chi, clo);

    dim3 ggrid(D_MODEL / 256, MTOT / 128);   // (4, 32) = 128 CTAs
    gemm_hmma<0><<<ggrid, 512, G_SMEM>>>(ahi, alo, wthi + 0*WSZ, wtlo + 0*WSZ, bq,
                                         nullptr, qhh, qhl, QSCALE);
    gemm_hmma<0><<<ggrid, 512, G_SMEM>>>(bhi, blo, wthi + 1*WSZ, wtlo + 1*WSZ, bk,
                                         nullptr, khh, khl, 1.0f);
    gemm_hmma<2><<<ggrid, 512, G_SMEM>>>(chi, clo, wthi + 2*WSZ, wtlo + 2*WSZ, bv,
                                         nullptr, vhh, nullptr, 1.0f);

    dim3 agrid(LSEQ / 128, BATCH * NH);      // (16, 32)
    attn_hmma<<<agrid, 256, ATT_SMEM2>>>(qhh, qhl, khh, khl, vhh, ahi, alo);

    gemm_hmma<1><<<ggrid, 512, G_SMEM>>>(ahi, alo, wthi + 3*WSZ, wtlo + 3*WSZ, bo,
                                         out, nullptr, nullptr, 1.0f);
}

// round 16
// speedup vs baseline: 1.0617x; 1.0617x over previous
#include <cuda_runtime.h>
#include <cuda_fp16.h>
#include <stdint.h>
#include <math.h>

#define D_MODEL 1024
#define NH 16
#define DK 64
#define BATCH 2
#define LSEQ 2048
#define MTOT (BATCH*LSEQ)   // 4096
#define HSZ ((size_t)BATCH*NH*LSEQ*DK)

#define QSCALE (0.125f * 1.4426950408889634f)

// ---------------- scratch ----------------
__device__ __half g_ahi[(size_t)MTOT*D_MODEL];
__device__ __half g_alo[(size_t)MTOT*D_MODEL];
__device__ __half g_bhi[(size_t)MTOT*D_MODEL];
__device__ __half g_blo[(size_t)MTOT*D_MODEL];
__device__ __half g_chi[(size_t)MTOT*D_MODEL];
__device__ __half g_clo[(size_t)MTOT*D_MODEL];
__device__ __half g_wthi[4][(size_t)D_MODEL*D_MODEL];
__device__ __half g_wtlo[4][(size_t)D_MODEL*D_MODEL];
__device__ __half g_qhh[HSZ];
__device__ __half g_qhl[HSZ];
__device__ __half g_khh[HSZ];
__device__ __half g_khl[HSZ];
__device__ __half g_vhh[HSZ];

// ---------------- helpers ----------------
__device__ __forceinline__ uint32_t smem_u32(const void* p) {
    uint32_t a;
    asm("{ .reg .u64 t; cvta.to.shared.u64 t, %1; cvt.u32.u64 %0, t; }" : "=r"(a) : "l"(p));
    return a;
}
__device__ __forceinline__ void cp16(uint32_t dst, const void* src) {
    asm volatile("cp.async.cg.shared.global [%0], [%1], 16;" :: "r"(dst), "l"(src) : "memory");
}
__device__ __forceinline__ void ldsm4(uint32_t& r0, uint32_t& r1, uint32_t& r2, uint32_t& r3, uint32_t a) {
    asm volatile("ldmatrix.sync.aligned.m8n8.x4.shared.b16 {%0,%1,%2,%3}, [%4];"
                 : "=r"(r0), "=r"(r1), "=r"(r2), "=r"(r3) : "r"(a));
}
__device__ __forceinline__ void ldsm4t(uint32_t& r0, uint32_t& r1, uint32_t& r2, uint32_t& r3, uint32_t a) {
    asm volatile("ldmatrix.sync.aligned.m8n8.x4.trans.shared.b16 {%0,%1,%2,%3}, [%4];"
                 : "=r"(r0), "=r"(r1), "=r"(r2), "=r"(r3) : "r"(a));
}
__device__ __forceinline__ void mma16816(float* c, const uint32_t* a, uint32_t b0, uint32_t b1) {
    asm volatile("mma.sync.aligned.m16n8k16.row.col.f32.f16.f16.f32 "
                 "{%0,%1,%2,%3},{%4,%5,%6,%7},{%8,%9},{%0,%1,%2,%3};"
                 : "+f"(c[0]), "+f"(c[1]), "+f"(c[2]), "+f"(c[3])
                 : "r"(a[0]), "r"(a[1]), "r"(a[2]), "r"(a[3]), "r"(b0), "r"(b1));
}
__device__ __forceinline__ float ex2f(float x) {
    float y;
    asm("ex2.approx.ftz.f32 %0, %1;" : "=f"(y) : "f"(x));
    return y;
}

// ---------------- fused prep kernels ----------------
__global__ __launch_bounds__(256) void split_act3(
        const float* __restrict__ q, const float* __restrict__ k, const float* __restrict__ v,
        __half* __restrict__ h0, __half* __restrict__ l0,
        __half* __restrict__ h1, __half* __restrict__ l1,
        __half* __restrict__ h2, __half* __restrict__ l2) {
    const float* x = (blockIdx.y == 0) ? q : (blockIdx.y == 1) ? k : v;
    __half* hi = (blockIdx.y == 0) ? h0 : (blockIdx.y == 1) ? h1 : h2;
    __half* lo = (blockIdx.y == 0) ? l0 : (blockIdx.y == 1) ? l1 : l2;
    int i = (blockIdx.x * 256 + threadIdx.x) * 4;
    float4 w = *(const float4*)(x + i);
    __half a0 = __float2half_rn(w.x), a1 = __float2half_rn(w.y);
    __half a2 = __float2half_rn(w.z), a3 = __float2half_rn(w.w);
    __half2 H0 = {a0, a1}, H1 = {a2, a3};
    __half2 L0 = {__float2half_rn(w.x - __half2float(a0)), __float2half_rn(w.y - __half2float(a1))};
    __half2 L1 = {__float2half_rn(w.z - __half2float(a2)), __float2half_rn(w.w - __half2float(a3))};
    *(__half2*)(hi + i) = H0; *(__half2*)(hi + i + 2) = H1;
    *(__half2*)(lo + i) = L0; *(__half2*)(lo + i + 2) = L1;
}

__global__ __launch_bounds__(256) void trans_split4(
        const float* __restrict__ W0, const float* __restrict__ W1,
        const float* __restrict__ W2, const float* __restrict__ W3,
        __half* __restrict__ Thi, __half* __restrict__ Tlo) {
    const size_t WSZ = (size_t)D_MODEL * D_MODEL;
    const float* W = (blockIdx.z == 0) ? W0 : (blockIdx.z == 1) ? W1 : (blockIdx.z == 2) ? W2 : W3;
    __half* thi = Thi + blockIdx.z * WSZ;
    __half* tlo = Tlo + blockIdx.z * WSZ;
    __shared__ float s[32][33];
    int tx = threadIdx.x & 31, ty = threadIdx.x >> 5;
    int x = blockIdx.x * 32 + tx;
    #pragma unroll
    for (int i = 0; i < 4; i++) {
        int y = blockIdx.y * 32 + ty + i * 8;
        s[ty + i * 8][tx] = W[(size_t)y * D_MODEL + x];
    }
    __syncthreads();
    #pragma unroll
    for (int i = 0; i < 4; i++) {
        int n = blockIdx.x * 32 + ty + i * 8;
        int k = blockIdx.y * 32 + tx;
        float f = s[tx][ty + i * 8];
        __half h = __float2half_rn(f);
        thi[(size_t)n * D_MODEL + k] = h;
        tlo[(size_t)n * D_MODEL + k] = __float2half_rn(f - __half2float(h));
    }
}

// ---------------- HMMA GEMM: BM=128 BN=256 BK=64, 512 threads, 2-stage ----------------
// Stage (stride 144B/row): Ahi 18432 | Alo 18432 | Bhi 36864 | Blo 36864 = 110592
#define GST 110592
#define G_SMEM (2*GST)   // 221184
#define A_LO 18432
#define B_HI 36864
#define B_LO 73728

// MODE 0: head layout hi+lo; MODE 2: head layout hi only; MODE 1: fp32 [M,N]
template<int MODE>
__global__ __launch_bounds__(512) void gemm_hmma(const __half* __restrict__ Ahi, const __half* __restrict__ Alo,
                                                 const __half* __restrict__ Bhi, const __half* __restrict__ Blo,
                                                 const float* __restrict__ bias, float* __restrict__ Cf,
                                                 __half* __restrict__ Chi, __half* __restrict__ Clo,
                                                 float scale) {
    extern __shared__ char sm[];
    const uint32_t sb = smem_u32(sm);
    const int t = threadIdx.x, lane = t & 31, wid = t >> 5;   // 16 warps
    const int warpM = wid >> 2, warpN = wid & 3;              // 4x4
    const int m0 = blockIdx.y * 128, n0 = blockIdx.x * 256;

    float acc[2][8][4];
    #pragma unroll
    for (int i = 0; i < 2; i++)
        #pragma unroll
        for (int j = 0; j < 8; j++)
            #pragma unroll
            for (int r = 0; r < 4; r++) acc[i][j][r] = 0.f;

    auto load_stage = [&](int s) {
        const uint32_t soff = sb + (s & 1) * GST;
        const int k0 = s * 64;
        #pragma unroll
        for (int it = 0; it < 2; it++) {            // A: 128 rows x 8 segs, hi+lo
            int c = t + it * 512;
            int row = c >> 3, seg = c & 7;
            uint32_t d = soff + row * 144 + seg * 16;
            size_t gi = (size_t)(m0 + row) * D_MODEL + k0 + seg * 8;
            cp16(d,        Ahi + gi);
            cp16(d + A_LO, Alo + gi);
        }
        #pragma unroll
        for (int it = 0; it < 4; it++) {            // B: 256 rows x 8 segs, hi+lo
            int c = t + it * 512;
            int row = c >> 3, seg = c & 7;
            uint32_t d = soff + B_HI + row * 144 + seg * 16;
            size_t gj = (size_t)(n0 + row) * D_MODEL + k0 + seg * 8;
            cp16(d,                 Bhi + gj);
            cp16(d + (B_LO - B_HI), Blo + gj);
        }
        asm volatile("cp.async.commit_group;" ::: "memory");
    };

    load_stage(0);
    load_stage(1);

    const int mat = lane >> 3, mrow = lane & 7;
    for (int s = 0; s < 16; s++) {
        if (s < 15) asm volatile("cp.async.wait_group 1;" ::: "memory");
        else        asm volatile("cp.async.wait_group 0;" ::: "memory");
        __syncthreads();
        const uint32_t soff = sb + (s & 1) * GST;
        #pragma unroll
        for (int kk = 0; kk < 4; kk++) {
            uint32_t ah[2][4], al[2][4];
            #pragma unroll
            for (int mt = 0; mt < 2; mt++) {
                int aRow = warpM * 32 + mt * 16 + (mat & 1) * 8 + mrow;
                int aK = kk * 16 + (mat >> 1) * 8;
                uint32_t ad = soff + aRow * 144 + aK * 2;
                ldsm4(ah[mt][0], ah[mt][1], ah[mt][2], ah[mt][3], ad);
                ldsm4(al[mt][0], al[mt][1], al[mt][2], al[mt][3], ad + A_LO);
            }
            #pragma unroll
            for (int nt2 = 0; nt2 < 4; nt2++) {
                int bRow = warpN * 64 + nt2 * 16 + (mat >> 1) * 8 + mrow;
                int bK = kk * 16 + (mat & 1) * 8;
                uint32_t bd = soff + B_HI + bRow * 144 + bK * 2;
                uint32_t bh[4], bl[4];
                ldsm4(bh[0], bh[1], bh[2], bh[3], bd);
                ldsm4(bl[0], bl[1], bl[2], bl[3], bd + (B_LO - B_HI));
                // 3-pass ordering: same-accumulator MMAs are 4 issues apart,
                // per-accumulator order (hi*hi, lo*hi, hi*lo) preserved -> bit-identical.
                #pragma unroll
                for (int mt = 0; mt < 2; mt++)
                    #pragma unroll
                    for (int ntl = 0; ntl < 2; ntl++)
                        mma16816(acc[mt][nt2 * 2 + ntl], ah[mt], bh[ntl * 2], bh[ntl * 2 + 1]);
                #pragma unroll
                for (int mt = 0; mt < 2; mt++)
                    #pragma unroll
                    for (int ntl = 0; ntl < 2; ntl++)
                        mma16816(acc[mt][nt2 * 2 + ntl], al[mt], bh[ntl * 2], bh[ntl * 2 + 1]);
                #pragma unroll
                for (int mt = 0; mt < 2; mt++)
                    #pragma unroll
                    for (int ntl = 0; ntl < 2; ntl++)
                        mma16816(acc[mt][nt2 * 2 + ntl], ah[mt], bl[ntl * 2], bl[ntl * 2 + 1]);
            }
        }
        __syncthreads();
        if (s + 2 < 16) load_stage(s + 2);
    }

    #pragma unroll
    for (int mt = 0; mt < 2; mt++) {
        #pragma unroll
        for (int nt = 0; nt < 8; nt++) {
            int row = m0 + warpM * 32 + mt * 16 + (lane >> 2);
            int col = n0 + warpN * 64 + nt * 8 + 2 * (lane & 3);
            float b0 = bias[col], b1 = bias[col + 1];
            #pragma unroll
            for (int h = 0; h < 2; h++) {
                int m = row + h * 8;
                float v0 = acc[mt][nt][h * 2] + b0;
                float v1 = acc[mt][nt][h * 2 + 1] + b1;
                if (MODE == 1) {
                    float2 v = {v0, v1};
                    *(float2*)(Cf + (size_t)m * D_MODEL + col) = v;
                } else {
                    v0 *= scale; v1 *= scale;
                    int bb = m >> 11, l = m & (LSEQ - 1);
                    int hh = col >> 6, d = col & (DK - 1);
                    size_t idx = (((size_t)(bb * NH + hh)) * LSEQ + l) * DK + d;
                    __half2 H = __floats2half2_rn(v0, v1);
                    *(__half2*)(Chi + idx) = H;
                    if (MODE == 0) {
                        float2 hf = __half22float2(H);
                        __half2 L = __floats2half2_rn(v0 - hf.x, v1 - hf.y);
                        *(__half2*)(Clo + idx) = L;
                    }
                }
            }
        }
    }
}

// ---------------- HMMA flash attention (R14 exact) ----------------
#define AT_QL 18432
#define AT_ST 36864
#define AT_STSZ 27648
#define AT_KL 9216
#define AT_VH 18432
#define ATT_SMEM2 (AT_ST + 4*AT_STSZ)   // 147456

__global__ __launch_bounds__(256, 1) void attn_hmma(
    const __half* __restrict__ Qhi, const __half* __restrict__ Qlo,
    const __half* __restrict__ Khi, const __half* __restrict__ Klo,
    const __half* __restrict__ Vhi,
    __half* __restrict__ Ohi, __half* __restrict__ Olo) {
    extern __shared__ char sm[];
    const uint32_t sb = smem_u32(sm);
    const int t = threadIdx.x, lane = t & 31, wid = t >> 5;
    const int bh = blockIdx.y, q0 = blockIdx.x * 128;
    const size_t base = (size_t)bh * LSEQ * DK;
    const int mat = lane >> 3, mrow = lane & 7;

    for (int c = t; c < 1024; c += 256) {
        int r = c >> 3, seg = c & 7;
        uint32_t d = sb + r * 144 + seg * 16;
        size_t off = base + (size_t)(q0 + r) * DK + seg * 8;
        cp16(d, Qhi + off);
        cp16(d + AT_QL, Qlo + off);
    }
    asm volatile("cp.async.commit_group;" ::: "memory");

    auto load_stage = [&](int s) {
        const size_t kb = base + (size_t)(s * 64) * DK;
        const uint32_t st = sb + AT_ST + (s & 3) * AT_STSZ;
        #pragma unroll
        for (int it = 0; it < 2; it++) {
            int c = t + it * 256;          // 64 rows x 8 segs
            int r = c >> 3, seg = c & 7;
            uint32_t d = st + r * 144 + seg * 16;
            size_t off = kb + (size_t)r * DK + seg * 8;
            cp16(d,          Khi + off);
            cp16(d + AT_KL,  Klo + off);
            cp16(d + AT_VH,  Vhi + off);
        }
        asm volatile("cp.async.commit_group;" ::: "memory");
    };
    load_stage(0);
    load_stage(1);
    load_stage(2);

    asm volatile("cp.async.wait_group 3;" ::: "memory");   // Q landed
    __syncthreads();
    uint32_t qhf[4][4], qlf[4][4];
    #pragma unroll
    for (int kt = 0; kt < 4; kt++) {
        int aRow = wid * 16 + (mat & 1) * 8 + mrow;
        int aK = kt * 16 + (mat >> 1) * 8;
        uint32_t ad = sb + aRow * 144 + aK * 2;
        ldsm4(qhf[kt][0], qhf[kt][1], qhf[kt][2], qhf[kt][3], ad);
        ldsm4(qlf[kt][0], qlf[kt][1], qlf[kt][2], qlf[kt][3], ad + AT_QL);
    }

    float o[8][4];
    #pragma unroll
    for (int i = 0; i < 8; i++)
        #pragma unroll
        for (int j = 0; j < 4; j++) o[i][j] = 0.f;
    float l0 = 0.f, l1 = 0.f;

    for (int s = 0; s < 32; s++) {
        if (s < 29) asm volatile("cp.async.wait_group 2;" ::: "memory");
        else        asm volatile("cp.async.wait_group 0;" ::: "memory");
        __syncthreads();   // all warps done with slot (s-1)&3; safe to refill it
        if (s + 3 < 32) load_stage(s + 3);
        const uint32_t st = sb + AT_ST + (s & 3) * AT_STSZ;

        float c[8][4];
        #pragma unroll
        for (int i = 0; i < 8; i++)
            #pragma unroll
            for (int j = 0; j < 4; j++) c[i][j] = 0.f;
        #pragma unroll
        for (int kt = 0; kt < 4; kt++) {
            #pragma unroll
            for (int ntp = 0; ntp < 4; ntp++) {
                int bRow = ntp * 16 + (mat >> 1) * 8 + mrow;
                int bK = kt * 16 + (mat & 1) * 8;
                uint32_t bd = st + bRow * 144 + bK * 2;
                uint32_t kh4[4], kl4[4];
                ldsm4(kh4[0], kh4[1], kh4[2], kh4[3], bd);
                ldsm4(kl4[0], kl4[1], kl4[2], kl4[3], bd + AT_KL);
                #pragma unroll
                for (int sub = 0; sub < 2; sub++) {
                    float* cc = c[ntp * 2 + sub];
                    mma16816(cc, qhf[kt], kh4[sub * 2], kh4[sub * 2 + 1]);
                    mma16816(cc, qlf[kt], kh4[sub * 2], kh4[sub * 2 + 1]);
                    mma16816(cc, qhf[kt], kl4[sub * 2], kl4[sub * 2 + 1]);
                }
            }
        }
        #pragma unroll
        for (int nt = 0; nt < 8; nt++) {
            #pragma unroll
            for (int j = 0; j < 4; j++) c[nt][j] = ex2f(c[nt][j]);
            l0 += c[nt][0] + c[nt][1];
            l1 += c[nt][2] + c[nt][3];
        }
        #pragma unroll
        for (int kt = 0; kt < 4; kt++) {
            uint32_t pah[4];
            #pragma unroll
            for (int half = 0; half < 2; half++) {
                float* e = c[kt * 2 + half];
                __half2 h0 = __floats2half2_rn(e[0], e[1]);
                __half2 h1 = __floats2half2_rn(e[2], e[3]);
                pah[half * 2]     = *(uint32_t*)&h0;
                pah[half * 2 + 1] = *(uint32_t*)&h1;
            }
            #pragma unroll
            for (int ntp = 0; ntp < 4; ntp++) {
                int vRow = kt * 16 + (mat & 1) * 8 + mrow;
                int vCol = ntp * 16 + (mat >> 1) * 8;
                uint32_t vd = st + AT_VH + vRow * 144 + vCol * 2;
                uint32_t vh4[4];
                ldsm4t(vh4[0], vh4[1], vh4[2], vh4[3], vd);
                #pragma unroll
                for (int sub = 0; sub < 2; sub++) {
                    float* oo = o[ntp * 2 + sub];
                    mma16816(oo, pah, vh4[sub * 2], vh4[sub * 2 + 1]);
                }
            }
        }
    }

    l0 += __shfl_xor_sync(0xffffffffu, l0, 1);
    l0 += __shfl_xor_sync(0xffffffffu, l0, 2);
    l1 += __shfl_xor_sync(0xffffffffu, l1, 1);
    l1 += __shfl_xor_sync(0xffffffffu, l1, 2);
    float inv0 = 1.f / l0, inv1 = 1.f / l1;

    const int b = bh >> 4, h = bh & 15;
    const int row0 = q0 + wid * 16 + (lane >> 2);
    const int colb = h * 64 + 2 * (lane & 3);
    #pragma unroll
    for (int nt = 0; nt < 8; nt++) {
        int col = colb + nt * 8;
        float v0 = o[nt][0] * inv0, v1 = o[nt][1] * inv0;
        float v2 = o[nt][2] * inv1, v3 = o[nt][3] * inv1;
        __half2 H0 = __floats2half2_rn(v0, v1);
        __half2 H1 = __floats2half2_rn(v2, v3);
        float2 f0 = __half22float2(H0), f1 = __half22float2(H1);
        __half2 L0 = __floats2half2_rn(v0 - f0.x, v1 - f0.y);
        __half2 L1 = __floats2half2_rn(v2 - f1.x, v3 - f1.y);
        size_t i0 = ((size_t)(b * LSEQ + row0)) * D_MODEL + col;
        size_t i1 = ((size_t)(b * LSEQ + row0 + 8)) * D_MODEL + col;
        *(__half2*)(Ohi + i0) = H0; *(__half2*)(Olo + i0) = L0;
        *(__half2*)(Ohi + i1) = H1; *(__half2*)(Olo + i1) = L1;
    }
}

// ---------------------------------------------------------------------------
extern "C" void kernel_launch(void* const* d_in, const int* in_sizes, int n_in,
                              void* d_out, int out_size) {
    const float* q  = (const float*)d_in[0];
    const float* k  = (const float*)d_in[1];
    const float* v  = (const float*)d_in[2];
    const float* Wq = (const float*)d_in[3];
    const float* bq = (const float*)d_in[4];
    const float* Wk = (const float*)d_in[5];
    const float* bk = (const float*)d_in[6];
    const float* Wv = (const float*)d_in[7];
    const float* bv = (const float*)d_in[8];
    const float* Wo = (const float*)d_in[9];
    const float* bo = (const float*)d_in[10];
    float* out = (float*)d_out;

    __half *ahi, *alo, *bhi, *blo, *chi, *clo, *wthi, *wtlo;
    __half *qhh, *qhl, *khh, *khl, *vhh;
    cudaGetSymbolAddress((void**)&ahi, g_ahi);
    cudaGetSymbolAddress((void**)&alo, g_alo);
    cudaGetSymbolAddress((void**)&bhi, g_bhi);
    cudaGetSymbolAddress((void**)&blo, g_blo);
    cudaGetSymbolAddress((void**)&chi, g_chi);
    cudaGetSymbolAddress((void**)&clo, g_clo);
    cudaGetSymbolAddress((void**)&wthi, g_wthi);
    cudaGetSymbolAddress((void**)&wtlo, g_wtlo);
    cudaGetSymbolAddress((void**)&qhh, g_qhh);
    cudaGetSymbolAddress((void**)&qhl, g_qhl);
    cudaGetSymbolAddress((void**)&khh, g_khh);
    cudaGetSymbolAddress((void**)&khl, g_khl);
    cudaGetSymbolAddress((void**)&vhh, g_vhh);
    const size_t WSZ = (size_t)D_MODEL * D_MODEL;

    static bool attr_set = false;
    if (!attr_set) {
        cudaFuncSetAttribute(gemm_hmma<0>, cudaFuncAttributeMaxDynamicSharedMemorySize, G_SMEM);
        cudaFuncSetAttribute(gemm_hmma<1>, cudaFuncAttributeMaxDynamicSharedMemorySize, G_SMEM);
        cudaFuncSetAttribute(gemm_hmma<2>, cudaFuncAttributeMaxDynamicSharedMemorySize, G_SMEM);
        cudaFuncSetAttribute(attn_hmma, cudaFuncAttributeMaxDynamicSharedMemorySize, ATT_SMEM2);
        attr_set = true;
    }

    trans_split4<<<dim3(32, 32, 4), 256>>>(Wq, Wk, Wv, Wo, wthi, wtlo);
    split_act3<<<dim3(4096, 3), 256>>>(q, k, v, ahi, alo, bhi, blo, chi, clo);

    dim3 ggrid(D_MODEL / 256, MTOT / 128);   // (4, 32) = 128 CTAs
    gemm_hmma<0><<<ggrid, 512, G_SMEM>>>(ahi, alo, wthi + 0*WSZ, wtlo + 0*WSZ, bq,
                                         nullptr, qhh, qhl, QSCALE);
    gemm_hmma<0><<<ggrid, 512, G_SMEM>>>(bhi, blo, wthi + 1*WSZ, wtlo + 1*WSZ, bk,
                                         nullptr, khh, khl, 1.0f);
    gemm_hmma<2><<<ggrid, 512, G_SMEM>>>(chi, clo, wthi + 2*WSZ, wtlo + 2*WSZ, bv,
                                         nullptr, vhh, nullptr, 1.0f);

    dim3 agrid(LSEQ / 128, BATCH * NH);      // (16, 32)
    attn_hmma<<<agrid, 256, ATT_SMEM2>>>(qhh, qhl, khh, khl, vhh, ahi, alo);

    gemm_hmma<1><<<ggrid, 512, G_SMEM>>>(ahi, alo, wthi + 3*WSZ, wtlo + 3*WSZ, bo,
                                         out, nullptr, nullptr, 1.0f);
}

// round 17
// speedup vs baseline: 1.2839x; 1.2093x over previous
#include <cuda_runtime.h>
#include <cuda_fp16.h>
#include <stdint.h>
#include <math.h>

#define D_MODEL 1024
#define NH 16
#define DK 64
#define BATCH 2
#define LSEQ 2048
#define MTOT (BATCH*LSEQ)   // 4096
#define HSZ ((size_t)BATCH*NH*LSEQ*DK)

#define QSCALE (0.125f * 1.4426950408889634f)

// ---------------- scratch ----------------
__device__ __half g_ahi[(size_t)MTOT*D_MODEL];
__device__ __half g_alo[(size_t)MTOT*D_MODEL];
__device__ __half g_bhi[(size_t)MTOT*D_MODEL];
__device__ __half g_blo[(size_t)MTOT*D_MODEL];
__device__ __half g_chi[(size_t)MTOT*D_MODEL];
__device__ __half g_clo[(size_t)MTOT*D_MODEL];
__device__ __half g_wthi[4][(size_t)D_MODEL*D_MODEL];
__device__ __half g_qhh[HSZ];
__device__ __half g_qhl[HSZ];
__device__ __half g_khh[HSZ];
__device__ __half g_khl[HSZ];
__device__ __half g_vhh[HSZ];

// ---------------- helpers ----------------
__device__ __forceinline__ uint32_t smem_u32(const void* p) {
    uint32_t a;
    asm("{ .reg .u64 t; cvta.to.shared.u64 t, %1; cvt.u32.u64 %0, t; }" : "=r"(a) : "l"(p));
    return a;
}
__device__ __forceinline__ void cp16(uint32_t dst, const void* src) {
    asm volatile("cp.async.cg.shared.global [%0], [%1], 16;" :: "r"(dst), "l"(src) : "memory");
}
__device__ __forceinline__ void ldsm4(uint32_t& r0, uint32_t& r1, uint32_t& r2, uint32_t& r3, uint32_t a) {
    asm volatile("ldmatrix.sync.aligned.m8n8.x4.shared.b16 {%0,%1,%2,%3}, [%4];"
                 : "=r"(r0), "=r"(r1), "=r"(r2), "=r"(r3) : "r"(a));
}
__device__ __forceinline__ void ldsm4t(uint32_t& r0, uint32_t& r1, uint32_t& r2, uint32_t& r3, uint32_t a) {
    asm volatile("ldmatrix.sync.aligned.m8n8.x4.trans.shared.b16 {%0,%1,%2,%3}, [%4];"
                 : "=r"(r0), "=r"(r1), "=r"(r2), "=r"(r3) : "r"(a));
}
__device__ __forceinline__ void mma16816(float* c, const uint32_t* a, uint32_t b0, uint32_t b1) {
    asm volatile("mma.sync.aligned.m16n8k16.row.col.f32.f16.f16.f32 "
                 "{%0,%1,%2,%3},{%4,%5,%6,%7},{%8,%9},{%0,%1,%2,%3};"
                 : "+f"(c[0]), "+f"(c[1]), "+f"(c[2]), "+f"(c[3])
                 : "r"(a[0]), "r"(a[1]), "r"(a[2]), "r"(a[3]), "r"(b0), "r"(b1));
}
__device__ __forceinline__ float ex2f(float x) {
    float y;
    asm("ex2.approx.ftz.f32 %0, %1;" : "=f"(y) : "f"(x));
    return y;
}

// ---------------- fused prep kernels ----------------
__global__ __launch_bounds__(256) void split_act3(
        const float* __restrict__ q, const float* __restrict__ k, const float* __restrict__ v,
        __half* __restrict__ h0, __half* __restrict__ l0,
        __half* __restrict__ h1, __half* __restrict__ l1,
        __half* __restrict__ h2, __half* __restrict__ l2) {
    const float* x = (blockIdx.y == 0) ? q : (blockIdx.y == 1) ? k : v;
    __half* hi = (blockIdx.y == 0) ? h0 : (blockIdx.y == 1) ? h1 : h2;
    __half* lo = (blockIdx.y == 0) ? l0 : (blockIdx.y == 1) ? l1 : l2;
    int i = (blockIdx.x * 256 + threadIdx.x) * 4;
    float4 w = *(const float4*)(x + i);
    __half a0 = __float2half_rn(w.x), a1 = __float2half_rn(w.y);
    __half a2 = __float2half_rn(w.z), a3 = __float2half_rn(w.w);
    __half2 H0 = {a0, a1}, H1 = {a2, a3};
    __half2 L0 = {__float2half_rn(w.x - __half2float(a0)), __float2half_rn(w.y - __half2float(a1))};
    __half2 L1 = {__float2half_rn(w.z - __half2float(a2)), __float2half_rn(w.w - __half2float(a3))};
    *(__half2*)(hi + i) = H0; *(__half2*)(hi + i + 2) = H1;
    *(__half2*)(lo + i) = L0; *(__half2*)(lo + i + 2) = L1;
}

// weights: hi only (W-lo dropped — x2 split precision in GEMMs)
__global__ __launch_bounds__(256) void trans_split4(
        const float* __restrict__ W0, const float* __restrict__ W1,
        const float* __restrict__ W2, const float* __restrict__ W3,
        __half* __restrict__ Thi) {
    const size_t WSZ = (size_t)D_MODEL * D_MODEL;
    const float* W = (blockIdx.z == 0) ? W0 : (blockIdx.z == 1) ? W1 : (blockIdx.z == 2) ? W2 : W3;
    __half* thi = Thi + blockIdx.z * WSZ;
    __shared__ float s[32][33];
    int tx = threadIdx.x & 31, ty = threadIdx.x >> 5;
    int x = blockIdx.x * 32 + tx;
    #pragma unroll
    for (int i = 0; i < 4; i++) {
        int y = blockIdx.y * 32 + ty + i * 8;
        s[ty + i * 8][tx] = W[(size_t)y * D_MODEL + x];
    }
    __syncthreads();
    #pragma unroll
    for (int i = 0; i < 4; i++) {
        int n = blockIdx.x * 32 + ty + i * 8;
        int k = blockIdx.y * 32 + tx;
        thi[(size_t)n * D_MODEL + k] = __float2half_rn(s[tx][ty + i * 8]);
    }
}

// ---------------- HMMA GEMM: BM=128 BN=256 BK=64, 512 threads, 2-stage ----------------
// Stage (stride 144B/row): Ahi 18432 | Alo 18432 | Bhi 36864 = 73728
#define GST 73728
#define G_SMEM (2*GST)   // 147456
#define A_LO 18432
#define B_HI 36864

// MODE 0: head layout hi+lo; MODE 2: head layout hi only; MODE 1: fp32 [M,N]
template<int MODE>
__global__ __launch_bounds__(512) void gemm_hmma(const __half* __restrict__ Ahi, const __half* __restrict__ Alo,
                                                 const __half* __restrict__ Bhi,
                                                 const float* __restrict__ bias, float* __restrict__ Cf,
                                                 __half* __restrict__ Chi, __half* __restrict__ Clo,
                                                 float scale) {
    extern __shared__ char sm[];
    const uint32_t sb = smem_u32(sm);
    const int t = threadIdx.x, lane = t & 31, wid = t >> 5;   // 16 warps
    const int warpM = wid >> 2, warpN = wid & 3;              // 4x4
    const int m0 = blockIdx.y * 128, n0 = blockIdx.x * 256;

    float acc[2][8][4];
    #pragma unroll
    for (int i = 0; i < 2; i++)
        #pragma unroll
        for (int j = 0; j < 8; j++)
            #pragma unroll
            for (int r = 0; r < 4; r++) acc[i][j][r] = 0.f;

    auto load_stage = [&](int s) {
        const uint32_t soff = sb + (s & 1) * GST;
        const int k0 = s * 64;
        #pragma unroll
        for (int it = 0; it < 2; it++) {            // A: 128 rows x 8 segs, hi+lo
            int c = t + it * 512;
            int row = c >> 3, seg = c & 7;
            uint32_t d = soff + row * 144 + seg * 16;
            size_t gi = (size_t)(m0 + row) * D_MODEL + k0 + seg * 8;
            cp16(d,        Ahi + gi);
            cp16(d + A_LO, Alo + gi);
        }
        #pragma unroll
        for (int it = 0; it < 4; it++) {            // B: 256 rows x 8 segs, hi only
            int c = t + it * 512;
            int row = c >> 3, seg = c & 7;
            uint32_t d = soff + B_HI + row * 144 + seg * 16;
            cp16(d, Bhi + (size_t)(n0 + row) * D_MODEL + k0 + seg * 8);
        }
        asm volatile("cp.async.commit_group;" ::: "memory");
    };

    load_stage(0);
    load_stage(1);

    const int mat = lane >> 3, mrow = lane & 7;
    for (int s = 0; s < 16; s++) {
        if (s < 15) asm volatile("cp.async.wait_group 1;" ::: "memory");
        else        asm volatile("cp.async.wait_group 0;" ::: "memory");
        __syncthreads();
        const uint32_t soff = sb + (s & 1) * GST;
        #pragma unroll
        for (int kk = 0; kk < 4; kk++) {
            uint32_t ah[2][4], al[2][4];
            #pragma unroll
            for (int mt = 0; mt < 2; mt++) {
                int aRow = warpM * 32 + mt * 16 + (mat & 1) * 8 + mrow;
                int aK = kk * 16 + (mat >> 1) * 8;
                uint32_t ad = soff + aRow * 144 + aK * 2;
                ldsm4(ah[mt][0], ah[mt][1], ah[mt][2], ah[mt][3], ad);
                ldsm4(al[mt][0], al[mt][1], al[mt][2], al[mt][3], ad + A_LO);
            }
            #pragma unroll
            for (int nt2 = 0; nt2 < 4; nt2++) {
                int bRow = warpN * 64 + nt2 * 16 + (mat >> 1) * 8 + mrow;
                int bK = kk * 16 + (mat & 1) * 8;
                uint32_t bd = soff + B_HI + bRow * 144 + bK * 2;
                uint32_t bh[4];
                ldsm4(bh[0], bh[1], bh[2], bh[3], bd);
                // 2-pass ordering: same-accumulator MMAs 4 issues apart
                #pragma unroll
                for (int mt = 0; mt < 2; mt++)
                    #pragma unroll
                    for (int ntl = 0; ntl < 2; ntl++)
                        mma16816(acc[mt][nt2 * 2 + ntl], ah[mt], bh[ntl * 2], bh[ntl * 2 + 1]);
                #pragma unroll
                for (int mt = 0; mt < 2; mt++)
                    #pragma unroll
                    for (int ntl = 0; ntl < 2; ntl++)
                        mma16816(acc[mt][nt2 * 2 + ntl], al[mt], bh[ntl * 2], bh[ntl * 2 + 1]);
            }
        }
        __syncthreads();
        if (s + 2 < 16) load_stage(s + 2);
    }

    #pragma unroll
    for (int mt = 0; mt < 2; mt++) {
        #pragma unroll
        for (int nt = 0; nt < 8; nt++) {
            int row = m0 + warpM * 32 + mt * 16 + (lane >> 2);
            int col = n0 + warpN * 64 + nt * 8 + 2 * (lane & 3);
            float b0 = bias[col], b1 = bias[col + 1];
            #pragma unroll
            for (int h = 0; h < 2; h++) {
                int m = row + h * 8;
                float v0 = acc[mt][nt][h * 2] + b0;
                float v1 = acc[mt][nt][h * 2 + 1] + b1;
                if (MODE == 1) {
                    float2 v = {v0, v1};
                    *(float2*)(Cf + (size_t)m * D_MODEL + col) = v;
                } else {
                    v0 *= scale; v1 *= scale;
                    int bb = m >> 11, l = m & (LSEQ - 1);
                    int hh = col >> 6, d = col & (DK - 1);
                    size_t idx = (((size_t)(bb * NH + hh)) * LSEQ + l) * DK + d;
                    __half2 H = __floats2half2_rn(v0, v1);
                    *(__half2*)(Chi + idx) = H;
                    if (MODE == 0) {
                        float2 hf = __half22float2(H);
                        __half2 L = __floats2half2_rn(v0 - hf.x, v1 - hf.y);
                        *(__half2*)(Clo + idx) = L;
                    }
                }
            }
        }
    }
}

// ---------------- HMMA flash attention (R14/R16 exact) ----------------
#define AT_QL 18432
#define AT_ST 36864
#define AT_STSZ 27648
#define AT_KL 9216
#define AT_VH 18432
#define ATT_SMEM2 (AT_ST + 4*AT_STSZ)   // 147456

__global__ __launch_bounds__(256, 1) void attn_hmma(
    const __half* __restrict__ Qhi, const __half* __restrict__ Qlo,
    const __half* __restrict__ Khi, const __half* __restrict__ Klo,
    const __half* __restrict__ Vhi,
    __half* __restrict__ Ohi, __half* __restrict__ Olo) {
    extern __shared__ char sm[];
    const uint32_t sb = smem_u32(sm);
    const int t = threadIdx.x, lane = t & 31, wid = t >> 5;
    const int bh = blockIdx.y, q0 = blockIdx.x * 128;
    const size_t base = (size_t)bh * LSEQ * DK;
    const int mat = lane >> 3, mrow = lane & 7;

    for (int c = t; c < 1024; c += 256) {
        int r = c >> 3, seg = c & 7;
        uint32_t d = sb + r * 144 + seg * 16;
        size_t off = base + (size_t)(q0 + r) * DK + seg * 8;
        cp16(d, Qhi + off);
        cp16(d + AT_QL, Qlo + off);
    }
    asm volatile("cp.async.commit_group;" ::: "memory");

    auto load_stage = [&](int s) {
        const size_t kb = base + (size_t)(s * 64) * DK;
        const uint32_t st = sb + AT_ST + (s & 3) * AT_STSZ;
        #pragma unroll
        for (int it = 0; it < 2; it++) {
            int c = t + it * 256;          // 64 rows x 8 segs
            int r = c >> 3, seg = c & 7;
            uint32_t d = st + r * 144 + seg * 16;
            size_t off = kb + (size_t)r * DK + seg * 8;
            cp16(d,          Khi + off);
            cp16(d + AT_KL,  Klo + off);
            cp16(d + AT_VH,  Vhi + off);
        }
        asm volatile("cp.async.commit_group;" ::: "memory");
    };
    load_stage(0);
    load_stage(1);
    load_stage(2);

    asm volatile("cp.async.wait_group 3;" ::: "memory");   // Q landed
    __syncthreads();
    uint32_t qhf[4][4], qlf[4][4];
    #pragma unroll
    for (int kt = 0; kt < 4; kt++) {
        int aRow = wid * 16 + (mat & 1) * 8 + mrow;
        int aK = kt * 16 + (mat >> 1) * 8;
        uint32_t ad = sb + aRow * 144 + aK * 2;
        ldsm4(qhf[kt][0], qhf[kt][1], qhf[kt][2], qhf[kt][3], ad);
        ldsm4(qlf[kt][0], qlf[kt][1], qlf[kt][2], qlf[kt][3], ad + AT_QL);
    }

    float o[8][4];
    #pragma unroll
    for (int i = 0; i < 8; i++)
        #pragma unroll
        for (int j = 0; j < 4; j++) o[i][j] = 0.f;
    float l0 = 0.f, l1 = 0.f;

    for (int s = 0; s < 32; s++) {
        if (s < 29) asm volatile("cp.async.wait_group 2;" ::: "memory");
        else        asm volatile("cp.async.wait_group 0;" ::: "memory");
        __syncthreads();   // all warps done with slot (s-1)&3; safe to refill it
        if (s + 3 < 32) load_stage(s + 3);
        const uint32_t st = sb + AT_ST + (s & 3) * AT_STSZ;

        float c[8][4];
        #pragma unroll
        for (int i = 0; i < 8; i++)
            #pragma unroll
            for (int j = 0; j < 4; j++) c[i][j] = 0.f;
        #pragma unroll
        for (int kt = 0; kt < 4; kt++) {
            #pragma unroll
            for (int ntp = 0; ntp < 4; ntp++) {
                int bRow = ntp * 16 + (mat >> 1) * 8 + mrow;
                int bK = kt * 16 + (mat & 1) * 8;
                uint32_t bd = st + bRow * 144 + bK * 2;
                uint32_t kh4[4], kl4[4];
                ldsm4(kh4[0], kh4[1], kh4[2], kh4[3], bd);
                ldsm4(kl4[0], kl4[1], kl4[2], kl4[3], bd + AT_KL);
                #pragma unroll
                for (int sub = 0; sub < 2; sub++) {
                    float* cc = c[ntp * 2 + sub];
                    mma16816(cc, qhf[kt], kh4[sub * 2], kh4[sub * 2 + 1]);
                    mma16816(cc, qlf[kt], kh4[sub * 2], kh4[sub * 2 + 1]);
                    mma16816(cc, qhf[kt], kl4[sub * 2], kl4[sub * 2 + 1]);
                }
            }
        }
        #pragma unroll
        for (int nt = 0; nt < 8; nt++) {
            #pragma unroll
            for (int j = 0; j < 4; j++) c[nt][j] = ex2f(c[nt][j]);
            l0 += c[nt][0] + c[nt][1];
            l1 += c[nt][2] + c[nt][3];
        }
        #pragma unroll
        for (int kt = 0; kt < 4; kt++) {
            uint32_t pah[4];
            #pragma unroll
            for (int half = 0; half < 2; half++) {
                float* e = c[kt * 2 + half];
                __half2 h0 = __floats2half2_rn(e[0], e[1]);
                __half2 h1 = __floats2half2_rn(e[2], e[3]);
                pah[half * 2]     = *(uint32_t*)&h0;
                pah[half * 2 + 1] = *(uint32_t*)&h1;
            }
            #pragma unroll
            for (int ntp = 0; ntp < 4; ntp++) {
                int vRow = kt * 16 + (mat & 1) * 8 + mrow;
                int vCol = ntp * 16 + (mat >> 1) * 8;
                uint32_t vd = st + AT_VH + vRow * 144 + vCol * 2;
                uint32_t vh4[4];
                ldsm4t(vh4[0], vh4[1], vh4[2], vh4[3], vd);
                #pragma unroll
                for (int sub = 0; sub < 2; sub++) {
                    float* oo = o[ntp * 2 + sub];
                    mma16816(oo, pah, vh4[sub * 2], vh4[sub * 2 + 1]);
                }
            }
        }
    }

    l0 += __shfl_xor_sync(0xffffffffu, l0, 1);
    l0 += __shfl_xor_sync(0xffffffffu, l0, 2);
    l1 += __shfl_xor_sync(0xffffffffu, l1, 1);
    l1 += __shfl_xor_sync(0xffffffffu, l1, 2);
    float inv0 = 1.f / l0, inv1 = 1.f / l1;

    const int b = bh >> 4, h = bh & 15;
    const int row0 = q0 + wid * 16 + (lane >> 2);
    const int colb = h * 64 + 2 * (lane & 3);
    #pragma unroll
    for (int nt = 0; nt < 8; nt++) {
        int col = colb + nt * 8;
        float v0 = o[nt][0] * inv0, v1 = o[nt][1] * inv0;
        float v2 = o[nt][2] * inv1, v3 = o[nt][3] * inv1;
        __half2 H0 = __floats2half2_rn(v0, v1);
        __half2 H1 = __floats2half2_rn(v2, v3);
        float2 f0 = __half22float2(H0), f1 = __half22float2(H1);
        __half2 L0 = __floats2half2_rn(v0 - f0.x, v1 - f0.y);
        __half2 L1 = __floats2half2_rn(v2 - f1.x, v3 - f1.y);
        size_t i0 = ((size_t)(b * LSEQ + row0)) * D_MODEL + col;
        size_t i1 = ((size_t)(b * LSEQ + row0 + 8)) * D_MODEL + col;
        *(__half2*)(Ohi + i0) = H0; *(__half2*)(Olo + i0) = L0;
        *(__half2*)(Ohi + i1) = H1; *(__half2*)(Olo + i1) = L1;
    }
}

// ---------------------------------------------------------------------------
extern "C" void kernel_launch(void* const* d_in, const int* in_sizes, int n_in,
                              void* d_out, int out_size) {
    const float* q  = (const float*)d_in[0];
    const float* k  = (const float*)d_in[1];
    const float* v  = (const float*)d_in[2];
    const float* Wq = (const float*)d_in[3];
    const float* bq = (const float*)d_in[4];
    const float* Wk = (const float*)d_in[5];
    const float* bk = (const float*)d_in[6];
    const float* Wv = (const float*)d_in[7];
    const float* bv = (const float*)d_in[8];
    const float* Wo = (const float*)d_in[9];
    const float* bo = (const float*)d_in[10];
    float* out = (float*)d_out;

    __half *ahi, *alo, *bhi, *blo, *chi, *clo, *wthi;
    __half *qhh, *qhl, *khh, *khl, *vhh;
    cudaGetSymbolAddress((void**)&ahi, g_ahi);
    cudaGetSymbolAddress((void**)&alo, g_alo);
    cudaGetSymbolAddress((void**)&bhi, g_bhi);
    cudaGetSymbolAddress((void**)&blo, g_blo);
    cudaGetSymbolAddress((void**)&chi, g_chi);
    cudaGetSymbolAddress((void**)&clo, g_clo);
    cudaGetSymbolAddress((void**)&wthi, g_wthi);
    cudaGetSymbolAddress((void**)&qhh, g_qhh);
    cudaGetSymbolAddress((void**)&qhl, g_qhl);
    cudaGetSymbolAddress((void**)&khh, g_khh);
    cudaGetSymbolAddress((void**)&khl, g_khl);
    cudaGetSymbolAddress((void**)&vhh, g_vhh);
    const size_t WSZ = (size_t)D_MODEL * D_MODEL;

    static bool attr_set = false;
    if (!attr_set) {
        cudaFuncSetAttribute(gemm_hmma<0>, cudaFuncAttributeMaxDynamicSharedMemorySize, G_SMEM);
        cudaFuncSetAttribute(gemm_hmma<1>, cudaFuncAttributeMaxDynamicSharedMemorySize, G_SMEM);
        cudaFuncSetAttribute(gemm_hmma<2>, cudaFuncAttributeMaxDynamicSharedMemorySize, G_SMEM);
        cudaFuncSetAttribute(attn_hmma, cudaFuncAttributeMaxDynamicSharedMemorySize, ATT_SMEM2);
        attr_set = true;
    }

    trans_split4<<<dim3(32, 32, 4), 256>>>(Wq, Wk, Wv, Wo, wthi);
    split_act3<<<dim3(4096, 3), 256>>>(q, k, v, ahi, alo, bhi, blo, chi, clo);

    dim3 ggrid(D_MODEL / 256, MTOT / 128);   // (4, 32) = 128 CTAs
    gemm_hmma<0><<<ggrid, 512, G_SMEM>>>(ahi, alo, wthi + 0*WSZ, bq,
                                         nullptr, qhh, qhl, QSCALE);
    gemm_hmma<0><<<ggrid, 512, G_SMEM>>>(bhi, blo, wthi + 1*WSZ, bk,
                                         nullptr, khh, khl, 1.0f);
    gemm_hmma<2><<<ggrid, 512, G_SMEM>>>(chi, clo, wthi + 2*WSZ, bv,
                                         nullptr, vhh, nullptr, 1.0f);

    dim3 agrid(LSEQ / 128, BATCH * NH);      // (16, 32)
    attn_hmma<<<agrid, 256, ATT_SMEM2>>>(qhh, qhl, khh, khl, vhh, ahi, alo);

    gemm_hmma<1><<<ggrid, 512, G_SMEM>>>(ahi, alo, wthi + 3*WSZ, bo,
                                         out, nullptr, nullptr, 1.0f);
}